// round 8
// baseline (speedup 1.0000x reference)
#include <cuda_runtime.h>
#include <cstdint>

#define CH_IN 32
#define CH_Y  16
#define IMG_H 256
#define IMG_W 256
#define NB    16
#define CHS   (IMG_H * IMG_W)   // channel stride (elements)
#define CHS4  (CHS / 4)
#define NT    128               // 2 rows/block, 64 thr/row, 4 px/thread

union F2U { float2 f; uint64_t u; };

// sm_103a packed dual-fp32 ops
__device__ __forceinline__ void fma2(uint64_t& d, uint64_t a, uint64_t b) {
    asm("fma.rn.f32x2 %0, %1, %2, %0;" : "+l"(d) : "l"(a), "l"(b));
}
__device__ __forceinline__ uint64_t mul2(uint64_t a, uint64_t b) {
    uint64_t d; asm("mul.rn.f32x2 %0, %1, %2;" : "=l"(d) : "l"(a), "l"(b)); return d;
}
__device__ __forceinline__ uint64_t add2(uint64_t a, uint64_t b) {
    uint64_t d; asm("add.rn.f32x2 %0, %1, %2;" : "=l"(d) : "l"(a), "l"(b)); return d;
}
__device__ __forceinline__ uint64_t dup2(float x) {
    uint64_t d; asm("mov.b64 %0, {%1, %1};" : "=l"(d) : "f"(x)); return d;
}
__device__ __forceinline__ uint64_t pack2(float lo, float hi) {
    uint64_t d; asm("mov.b64 %0, {%1, %2};" : "=l"(d) : "f"(lo), "f"(hi)); return d;
}

// smem carve offsets (bytes)
#define SM_P    0                               // p rows: 2 * 32KB
#define SM_WQ   (SM_P + 2 * CH_IN * IMG_W * 4)  // wqT: 256 float2 (2KB)
#define SM_WK   (SM_WQ + 2048)
#define SM_WV   (SM_WK + 2048)
#define SM_WY   (SM_WV + 2048)                  // wy: 128 float4 (2KB)
#define SM_BQ   (SM_WY + 2048)                  // bq2/bk2/bv2: 8 float2 each
#define SM_BK   (SM_BQ + 64)
#define SM_BV   (SM_BK + 64)
#define SM_BY   (SM_BV + 64)                    // by: 32 floats
#define SM_RED  (SM_BY + 128)                   // red: 4 warps x 8 u64
#define SM_TOT  (SM_RED + 256 + 128)

// 4 px/thread, o-split halves, o-packed FFMA2 (R6-proven formulation).
__global__ void __launch_bounds__(NT, 3) cross_attn_kernel(
    const float* __restrict__ cin, const float* __restrict__ pin,
    const float* __restrict__ Wq,  const float* __restrict__ bq,
    const float* __restrict__ Wk,  const float* __restrict__ bk,
    const float* __restrict__ Wv,  const float* __restrict__ bv,
    const float* __restrict__ Wy,  const float* __restrict__ by,
    float* __restrict__ out)
{
    extern __shared__ char smraw[];
    float4*   sp4  = (float4*)(smraw + SM_P);
    float2*   wqT  = (float2*)(smraw + SM_WQ);   // [c][o2] = (W[2o2][c],W[2o2+1][c])
    float2*   wkT  = (float2*)(smraw + SM_WK);
    float2*   wvT  = (float2*)(smraw + SM_WV);
    float4*   wy_s = (float4*)(smraw + SM_WY);
    float2*   bq2  = (float2*)(smraw + SM_BQ);
    float2*   bk2  = (float2*)(smraw + SM_BK);
    float2*   bv2  = (float2*)(smraw + SM_BV);
    float*    by_s = (float*) (smraw + SM_BY);
    uint64_t* red  = (uint64_t*)(smraw + SM_RED);   // [warp][o2]

    const int tid = threadIdx.x;
    const int t   = tid & 63;          // position within row (float4 slot)
    const int r   = tid >> 6;          // row within block (0/1)

    // ---- weight setup: transpose to [c][o2] natural-pair layout ----
#pragma unroll
    for (int s = 0; s < 2; s++) {
        int i = tid * 2 + s;           // 0..255
        int c = i >> 3, o2 = i & 7;
        wqT[i] = make_float2(Wq[(2*o2)*CH_IN + c], Wq[(2*o2+1)*CH_IN + c]);
        wkT[i] = make_float2(Wk[(2*o2)*CH_IN + c], Wk[(2*o2+1)*CH_IN + c]);
        wvT[i] = make_float2(Wv[(2*o2)*CH_IN + c], Wv[(2*o2+1)*CH_IN + c]);
    }
    wy_s[tid] = ((const float4*)Wy)[tid];        // o contiguous in rows
    if (tid < 8) {
        bq2[tid] = make_float2(bq[2*tid], bq[2*tid+1]);
        bk2[tid] = make_float2(bk[2*tid], bk[2*tid+1]);
        bv2[tid] = make_float2(bv[2*tid], bv[2*tid+1]);
    }
    if (tid < CH_IN) by_s[tid] = by[tid];

    const int h0 = (blockIdx.x & 127) * 2;
    const int b  = blockIdx.x >> 7;
    const size_t base = (size_t)b * CH_IN * CHS + (size_t)(h0 + r) * IMG_W;

    const float4* cg = (const float4*)(cin + base);
    const float4* pg = (const float4*)(pin + base);
    float4* oyg = (float4*)(out + (size_t)b * 2 * CH_IN * CHS + (size_t)(h0 + r) * IMG_W);
    float4* ocg = oyg + (size_t)CH_IN * CHS4;    // concat(c) half

    // ---------------- Phase 0: stage p row (this thread's row) ----------------
#pragma unroll
    for (int blk = 0; blk < 4; blk++) {
        float4 pb[8];
#pragma unroll
        for (int i = 0; i < 8; i++) {
            int idx = t + (blk * 8 + i) * 64;    // = ch*64 + w4
            pb[i] = pg[(size_t)(idx >> 6) * CHS4 + (idx & 63)];
        }
#pragma unroll
        for (int i = 0; i < 8; i++)
            sp4[r * 2048 + t + (blk * 8 + i) * 64] = pb[i];
    }
    __syncthreads();

    // ---------------- q,k projection: two o-halves ----------------
    uint64_t e[4][8];                  // [px][o2] packed (o 2o2, 2o2+1)

#pragma unroll
    for (int h4 = 0; h4 < 2; h4++) {   // o-half: o2 in [4*h4, 4*h4+4)
        uint64_t q[4][4], k[4][4];
#pragma unroll
        for (int ol = 0; ol < 4; ol++) {
            F2U tq; tq.f = bq2[h4 * 4 + ol];
            F2U tk; tk.f = bk2[h4 * 4 + ol];
#pragma unroll
            for (int px = 0; px < 4; px++) { q[px][ol] = tq.u; k[px][ol] = tk.u; }
        }

#pragma unroll
        for (int c4 = 0; c4 < CH_IN / 4; c4++) {
            float4 cf[4], pf[4];
#pragma unroll
            for (int j = 0; j < 4; j++) {
                int ch = c4 * 4 + j;
                cf[j] = cg[(size_t)ch * CHS4 + t];           // L2-resident
                pf[j] = sp4[r * 2048 + ch * 64 + t];
            }
            if (h4 == 0) {                                   // concat write-through
#pragma unroll
                for (int j = 0; j < 4; j++)
                    ocg[(size_t)(c4 * 4 + j) * CHS4 + t] = cf[j];
            }
#pragma unroll
            for (int j = 0; j < 4; j++) {
                const int ch = c4 * 4 + j;
                uint64_t cd[4] = { dup2(cf[j].x), dup2(cf[j].y),
                                   dup2(cf[j].z), dup2(cf[j].w) };
                uint64_t pd[4] = { dup2(pf[j].x), dup2(pf[j].y),
                                   dup2(pf[j].z), dup2(pf[j].w) };
#pragma unroll
                for (int m = 0; m < 2; m++) {                // 2 o2 per LDS.128
                    ulonglong2 wq2 = *(const ulonglong2*)&wqT[ch * 8 + h4 * 4 + m * 2];
                    ulonglong2 wk2 = *(const ulonglong2*)&wkT[ch * 8 + h4 * 4 + m * 2];
#pragma unroll
                    for (int px = 0; px < 4; px++) {
                        fma2(q[px][2*m+0], wq2.x, cd[px]);
                        fma2(q[px][2*m+1], wq2.y, cd[px]);
                        fma2(k[px][2*m+0], wk2.x, pd[px]);
                        fma2(k[px][2*m+1], wk2.y, pd[px]);
                    }
                }
            }
        }

        // exp(q*k) for this o-half. No max-subtraction: |q*k| O(1..10),
        // fp32 exp safe; identical after normalization.
#pragma unroll
        for (int px = 0; px < 4; px++)
#pragma unroll
            for (int ol = 0; ol < 4; ol++) {
                F2U pr; pr.u = mul2(q[px][ol], k[px][ol]);
                e[px][h4 * 4 + ol] = pack2(__expf(pr.f.x), __expf(pr.f.y));
            }
    }

    // ---------------- softmax over width (256 px = 64 thr x 4 px) ----------
    const int lane = tid & 31;
    const int wrp  = tid >> 5;         // warps 2r, 2r+1 belong to row r
#pragma unroll
    for (int o2 = 0; o2 < 8; o2++) {
        uint64_t s = add2(add2(e[0][o2], e[1][o2]), add2(e[2][o2], e[3][o2]));
#pragma unroll
        for (int d = 16; d > 0; d >>= 1)
            s = add2(s, __shfl_xor_sync(0xffffffffu, (unsigned long long)s, d));
        if (lane == 0) red[wrp * 8 + o2] = s;
    }
    __syncthreads();

#pragma unroll
    for (int o2 = 0; o2 < 8; o2++) {
        F2U tot; tot.u = add2(red[(2*r) * 8 + o2], red[(2*r+1) * 8 + o2]);
        uint64_t inv = pack2(__frcp_rn(tot.f.x), __frcp_rn(tot.f.y));
#pragma unroll
        for (int px = 0; px < 4; px++)
            e[px][o2] = mul2(e[px][o2], inv);    // fold 1/sum into e
    }

    // ---------------- v projection: two o-halves, y folded in ----------------
#pragma unroll
    for (int h4 = 0; h4 < 2; h4++) {
        uint64_t v[4][4];
#pragma unroll
        for (int ol = 0; ol < 4; ol++) {
            F2U tv; tv.f = bv2[h4 * 4 + ol];
#pragma unroll
            for (int px = 0; px < 4; px++) v[px][ol] = tv.u;
        }
#pragma unroll
        for (int c4 = 0; c4 < CH_IN / 4; c4++) {
            float4 pf[4];
#pragma unroll
            for (int j = 0; j < 4; j++)
                pf[j] = sp4[r * 2048 + (c4 * 4 + j) * 64 + t];
#pragma unroll
            for (int j = 0; j < 4; j++) {
                const int ch = c4 * 4 + j;
                uint64_t pd[4] = { dup2(pf[j].x), dup2(pf[j].y),
                                   dup2(pf[j].z), dup2(pf[j].w) };
#pragma unroll
                for (int m = 0; m < 2; m++) {
                    ulonglong2 wv2 = *(const ulonglong2*)&wvT[ch * 8 + h4 * 4 + m * 2];
#pragma unroll
                    for (int px = 0; px < 4; px++) {
                        fma2(v[px][2*m+0], wv2.x, pd[px]);
                        fma2(v[px][2*m+1], wv2.y, pd[px]);
                    }
                }
            }
        }
        // y = softmax * v for this o-half (overwrite e)
#pragma unroll
        for (int px = 0; px < 4; px++)
#pragma unroll
            for (int ol = 0; ol < 4; ol++)
                e[px][h4 * 4 + ol] = mul2(e[px][h4 * 4 + ol], v[px][ol]);
    }

    // ---------------- output conv1x1 ----------------
    const ulonglong2* wyu2 = (const ulonglong2*)wy_s;   // 4 per ic, o-pairs
#pragma unroll
    for (int ic = 0; ic < CH_IN; ic++) {
        uint64_t a0 = pack2(by_s[ic], 0.f);
        uint64_t acc[4] = { a0, a0, a0, a0 };
#pragma unroll
        for (int m = 0; m < 4; m++) {
            ulonglong2 w = wyu2[ic * 4 + m];            // o-pairs (2m, 2m+1)
#pragma unroll
            for (int px = 0; px < 4; px++) {
                fma2(acc[px], w.x, e[px][2*m+0]);
                fma2(acc[px], w.y, e[px][2*m+1]);
            }
        }
        F2U r0, r1, r2, r3;
        r0.u = acc[0]; r1.u = acc[1]; r2.u = acc[2]; r3.u = acc[3];
        oyg[(size_t)ic * CHS4 + t] = make_float4(r0.f.x + r0.f.y, r1.f.x + r1.f.y,
                                                 r2.f.x + r2.f.y, r3.f.x + r3.f.y);
    }
}

extern "C" void kernel_launch(void* const* d_in, const int* in_sizes, int n_in,
                              void* d_out, int out_size)
{
    cudaFuncSetAttribute(cross_attn_kernel,
                         cudaFuncAttributeMaxDynamicSharedMemorySize, SM_TOT);
    cross_attn_kernel<<<NB * IMG_H / 2, NT, SM_TOT>>>(
        (const float*)d_in[0],  // c
        (const float*)d_in[1],  // p
        (const float*)d_in[2],  // Wq
        (const float*)d_in[3],  // bq
        (const float*)d_in[4],  // Wk
        (const float*)d_in[5],  // bk
        (const float*)d_in[6],  // Wv
        (const float*)d_in[7],  // bv
        (const float*)d_in[8],  // Wy
        (const float*)d_in[9],  // by
        (float*)d_out);
}

// round 9
// speedup vs baseline: 1.3834x; 1.3834x over previous
#include <cuda_runtime.h>
#include <cstdint>

#define CH_IN 32
#define CH_Y  16
#define IMG_H 256
#define IMG_W 256
#define NB    16
#define CHS   (IMG_H * IMG_W)   // channel stride (elements)
#define CHS4  (CHS / 4)
#define NT    128               // one (b,h) row; thread = (px-group, o-half)

union F2U { float2 f; uint64_t u; };

// sm_103a packed dual-fp32 ops
__device__ __forceinline__ void fma2(uint64_t& d, uint64_t a, uint64_t b) {
    asm("fma.rn.f32x2 %0, %1, %2, %0;" : "+l"(d) : "l"(a), "l"(b));
}
__device__ __forceinline__ uint64_t mul2(uint64_t a, uint64_t b) {
    uint64_t d; asm("mul.rn.f32x2 %0, %1, %2;" : "=l"(d) : "l"(a), "l"(b)); return d;
}
__device__ __forceinline__ uint64_t add2(uint64_t a, uint64_t b) {
    uint64_t d; asm("add.rn.f32x2 %0, %1, %2;" : "=l"(d) : "l"(a), "l"(b)); return d;
}
__device__ __forceinline__ uint64_t dup2(float x) {
    uint64_t d; asm("mov.b64 %0, {%1, %1};" : "=l"(d) : "f"(x)); return d;
}
__device__ __forceinline__ uint64_t pack2(float lo, float hi) {
    uint64_t d; asm("mov.b64 %0, {%1, %2};" : "=l"(d) : "f"(lo), "f"(hi)); return d;
}

// Thread (t6, half): pixels w = 4*t6..4*t6+3, output channels o = 8*half..+8.
// Weight/wy traffic per thread halved vs R6; accumulators stay at 64 regs.
__global__ void __launch_bounds__(NT, 4) cross_attn_kernel(
    const float* __restrict__ cin, const float* __restrict__ pin,
    const float* __restrict__ Wq,  const float* __restrict__ bq,
    const float* __restrict__ Wk,  const float* __restrict__ bk,
    const float* __restrict__ Wv,  const float* __restrict__ bv,
    const float* __restrict__ Wy,  const float* __restrict__ by,
    float* __restrict__ out)
{
    __shared__ float4   sp4[CH_IN * IMG_W / 4];   // 32KB p row; reused as ybuf
    __shared__ __align__(16) float2 wqT[CH_IN * 8];  // [c][o2] natural pairs
    __shared__ __align__(16) float2 wkT[CH_IN * 8];
    __shared__ __align__(16) float2 wvT[CH_IN * 8];
    __shared__ __align__(16) float4 wy_s[CH_IN * CH_Y / 4];
    __shared__ float2   bq2[8], bk2[8], bv2[8];
    __shared__ float    by_s[CH_IN];
    __shared__ uint64_t red[4][4];                // [warp][local o2]

    const int tid  = threadIdx.x;
    const int t6   = tid & 63;        // pixel group (float4 slot in row)
    const int half = tid >> 6;        // o-half: o2 in [4*half, 4*half+4)

    // ---- weight setup: transpose to [c][o2] natural-pair layout ----
#pragma unroll
    for (int s = 0; s < 2; s++) {
        int i = tid * 2 + s;          // 0..255
        int c = i >> 3, o2 = i & 7;
        wqT[i] = make_float2(Wq[(2*o2)*CH_IN + c], Wq[(2*o2+1)*CH_IN + c]);
        wkT[i] = make_float2(Wk[(2*o2)*CH_IN + c], Wk[(2*o2+1)*CH_IN + c]);
        wvT[i] = make_float2(Wv[(2*o2)*CH_IN + c], Wv[(2*o2+1)*CH_IN + c]);
    }
    wy_s[tid] = ((const float4*)Wy)[tid];
    if (tid < 8) {
        bq2[tid] = make_float2(bq[2*tid], bq[2*tid+1]);
        bk2[tid] = make_float2(bk[2*tid], bk[2*tid+1]);
        bv2[tid] = make_float2(bv[2*tid], bv[2*tid+1]);
    }
    if (tid < CH_IN) by_s[tid] = by[tid];

    const int h = blockIdx.x & (IMG_H - 1);
    const int b = blockIdx.x >> 8;
    const size_t base = (size_t)b * CH_IN * CHS + (size_t)h * IMG_W;

    const float4* cg = (const float4*)(cin + base);
    const float4* pg = (const float4*)(pin + base);
    float4* oyg = (float4*)(out + (size_t)b * 2 * CH_IN * CHS + (size_t)h * IMG_W);
    float4* ocg = oyg + (size_t)CH_IN * CHS4;     // concat(c) half

    // ---------------- Phase 1: stage p + concat copy of c ----------------
#pragma unroll
    for (int halfb = 0; halfb < 2; halfb++) {
        float4 cb[8], pb[8];
#pragma unroll
        for (int i = 0; i < 8; i++) {
            int idx = tid + (halfb * 8 + i) * NT;         // = ch*64 + w4
            int ch = idx >> 6, w4 = idx & 63;
            cb[i] = cg[(size_t)ch * CHS4 + w4];
            pb[i] = pg[(size_t)ch * CHS4 + w4];
        }
#pragma unroll
        for (int i = 0; i < 8; i++) {
            int idx = tid + (halfb * 8 + i) * NT;
            int ch = idx >> 6, w4 = idx & 63;
            ocg[(size_t)ch * CHS4 + w4] = cb[i];
            sp4[idx] = pb[i];
        }
    }
    __syncthreads();

    // ---------------- q,k projection (my o-half only) ----------------
    uint64_t q[4][4], k[4][4];        // [px][local o2]
#pragma unroll
    for (int ol = 0; ol < 4; ol++) {
        F2U tq; tq.f = bq2[half * 4 + ol];
        F2U tk; tk.f = bk2[half * 4 + ol];
#pragma unroll
        for (int px = 0; px < 4; px++) { q[px][ol] = tq.u; k[px][ol] = tk.u; }
    }

#pragma unroll
    for (int c4 = 0; c4 < CH_IN / 4; c4++) {
        float4 cf[4], pf[4];
#pragma unroll
        for (int j = 0; j < 4; j++) {
            int ch = c4 * 4 + j;
            cf[j] = cg[(size_t)ch * CHS4 + t6];           // L2-resident re-read
            pf[j] = sp4[ch * 64 + t6];
        }
#pragma unroll
        for (int j = 0; j < 4; j++) {
            const int ch = c4 * 4 + j;
            uint64_t cd[4] = { dup2(cf[j].x), dup2(cf[j].y),
                               dup2(cf[j].z), dup2(cf[j].w) };
            uint64_t pd[4] = { dup2(pf[j].x), dup2(pf[j].y),
                               dup2(pf[j].z), dup2(pf[j].w) };
#pragma unroll
            for (int m = 0; m < 2; m++) {                 // 2 local o2 / LDS.128
                ulonglong2 wq2 = *(const ulonglong2*)&wqT[ch * 8 + half * 4 + m * 2];
                ulonglong2 wk2 = *(const ulonglong2*)&wkT[ch * 8 + half * 4 + m * 2];
#pragma unroll
                for (int px = 0; px < 4; px++) {
                    fma2(q[px][2*m+0], wq2.x, cd[px]);
                    fma2(q[px][2*m+1], wq2.y, cd[px]);
                    fma2(k[px][2*m+0], wk2.x, pd[px]);
                    fma2(k[px][2*m+1], wk2.y, pd[px]);
                }
            }
        }
    }

    // exp(q*k). No max-subtraction: |q*k| O(1..10); fp32 exp safe, identical
    // after normalization.
    uint64_t e[4][4];
#pragma unroll
    for (int px = 0; px < 4; px++)
#pragma unroll
        for (int ol = 0; ol < 4; ol++) {
            F2U pr; pr.u = mul2(q[px][ol], k[px][ol]);
            e[px][ol] = pack2(__expf(pr.f.x), __expf(pr.f.y));
        }

    // -------- softmax over width: reduce within my o-half group --------
    const int lane = tid & 31;
    const int wrp  = tid >> 5;        // warps {2*half, 2*half+1} form my group
#pragma unroll
    for (int ol = 0; ol < 4; ol++) {
        uint64_t s = add2(add2(e[0][ol], e[1][ol]), add2(e[2][ol], e[3][ol]));
#pragma unroll
        for (int d = 16; d > 0; d >>= 1)
            s = add2(s, __shfl_xor_sync(0xffffffffu, (unsigned long long)s, d));
        if (lane == 0) red[wrp][ol] = s;
    }
    __syncthreads();

#pragma unroll
    for (int ol = 0; ol < 4; ol++) {
        F2U tot; tot.u = add2(red[2*half][ol], red[2*half+1][ol]);
        uint64_t inv = pack2(__frcp_rn(tot.f.x), __frcp_rn(tot.f.y));
#pragma unroll
        for (int px = 0; px < 4; px++)
            e[px][ol] = mul2(e[px][ol], inv);             // fold 1/sum into e
    }

    // ---------------- v projection (my o-half), y folded in ----------------
    {
        uint64_t v[4][4];
#pragma unroll
        for (int ol = 0; ol < 4; ol++) {
            F2U tv; tv.f = bv2[half * 4 + ol];
#pragma unroll
            for (int px = 0; px < 4; px++) v[px][ol] = tv.u;
        }
#pragma unroll
        for (int c4 = 0; c4 < CH_IN / 4; c4++) {
            float4 pf[4];
#pragma unroll
            for (int j = 0; j < 4; j++)
                pf[j] = sp4[(c4 * 4 + j) * 64 + t6];
#pragma unroll
            for (int j = 0; j < 4; j++) {
                const int ch = c4 * 4 + j;
                uint64_t pd[4] = { dup2(pf[j].x), dup2(pf[j].y),
                                   dup2(pf[j].z), dup2(pf[j].w) };
#pragma unroll
                for (int m = 0; m < 2; m++) {
                    ulonglong2 wv2 = *(const ulonglong2*)&wvT[ch * 8 + half * 4 + m * 2];
#pragma unroll
                    for (int px = 0; px < 4; px++) {
                        fma2(v[px][2*m+0], wv2.x, pd[px]);
                        fma2(v[px][2*m+1], wv2.y, pd[px]);
                    }
                }
            }
        }
#pragma unroll
        for (int px = 0; px < 4; px++)
#pragma unroll
            for (int ol = 0; ol < 4; ol++)
                e[px][ol] = mul2(e[px][ol], v[px][ol]);   // y = softmax * v
    }

    // ---------------- y exchange via smem (overlay on dead p region) -------
    __syncthreads();                  // all p reads done before overwrite
    uint64_t* ybuf = (uint64_t*)sp4;  // [o2*4+px][group]: conflict-free
#pragma unroll
    for (int ol = 0; ol < 4; ol++)
#pragma unroll
        for (int px = 0; px < 4; px++)
            ybuf[((half * 4 + ol) * 4 + px) * 64 + t6] = e[px][ol];
    __syncthreads();

    uint64_t yall[4][8];              // [px][global o2]
#pragma unroll
    for (int o2 = 0; o2 < 8; o2++)
#pragma unroll
        for (int px = 0; px < 4; px++)
            yall[px][o2] = ybuf[(o2 * 4 + px) * 64 + t6];

    // ---------------- output conv1x1: my ic-half only ----------------
    const ulonglong2* wyu2 = (const ulonglong2*)wy_s;     // 4 per ic, o-pairs
    const int icb = half * 16;
#pragma unroll
    for (int icl = 0; icl < 16; icl++) {
        const int ic = icb + icl;
        uint64_t a0 = pack2(by_s[ic], 0.f);
        uint64_t acc[4] = { a0, a0, a0, a0 };
#pragma unroll
        for (int m = 0; m < 4; m++) {
            ulonglong2 w = wyu2[ic * 4 + m];              // o-pairs (2m, 2m+1)
#pragma unroll
            for (int px = 0; px < 4; px++) {
                fma2(acc[px], w.x, yall[px][2*m+0]);
                fma2(acc[px], w.y, yall[px][2*m+1]);
            }
        }
        F2U r0, r1, r2, r3;
        r0.u = acc[0]; r1.u = acc[1]; r2.u = acc[2]; r3.u = acc[3];
        oyg[(size_t)ic * CHS4 + t6] = make_float4(r0.f.x + r0.f.y, r1.f.x + r1.f.y,
                                                  r2.f.x + r2.f.y, r3.f.x + r3.f.y);
    }
}

extern "C" void kernel_launch(void* const* d_in, const int* in_sizes, int n_in,
                              void* d_out, int out_size)
{
    cross_attn_kernel<<<NB * IMG_H, NT>>>(
        (const float*)d_in[0],  // c
        (const float*)d_in[1],  // p
        (const float*)d_in[2],  // Wq
        (const float*)d_in[3],  // bq
        (const float*)d_in[4],  // Wk
        (const float*)d_in[5],  // bk
        (const float*)d_in[6],  // Wv
        (const float*)d_in[7],  // bv
        (const float*)d_in[8],  // Wy
        (const float*)d_in[9],  // by
        (float*)d_out);
}

// round 10
// speedup vs baseline: 1.8790x; 1.3582x over previous
#include <cuda_runtime.h>
#include <cstdint>

#define CH_IN 32
#define CH_Y  16
#define IMG_H 256
#define IMG_W 256
#define NB    16
#define CHS   (IMG_H * IMG_W)   // channel stride (elements)
#define CHS4  (CHS / 4)
#define CHS2  (CHS / 2)
#define NT    256               // one (b,h) row; thread = (px-pair, o-half)

union F2U { float2 f; uint64_t u; };

// sm_103a packed dual-fp32 ops
__device__ __forceinline__ void fma2(uint64_t& d, uint64_t a, uint64_t b) {
    asm("fma.rn.f32x2 %0, %1, %2, %0;" : "+l"(d) : "l"(a), "l"(b));
}
__device__ __forceinline__ uint64_t mul2(uint64_t a, uint64_t b) {
    uint64_t d; asm("mul.rn.f32x2 %0, %1, %2;" : "=l"(d) : "l"(a), "l"(b)); return d;
}
__device__ __forceinline__ uint64_t add2(uint64_t a, uint64_t b) {
    uint64_t d; asm("add.rn.f32x2 %0, %1, %2;" : "=l"(d) : "l"(a), "l"(b)); return d;
}
__device__ __forceinline__ uint64_t dup2(float x) {
    uint64_t d; asm("mov.b64 %0, {%1, %1};" : "=l"(d) : "f"(x)); return d;
}
__device__ __forceinline__ uint64_t pack2(float lo, float hi) {
    uint64_t d; asm("mov.b64 %0, {%1, %2};" : "=l"(d) : "f"(lo), "f"(hi)); return d;
}

// Thread (t, half): pixels w = 2t, 2t+1; output channels o in [8*half, 8*half+8).
// Warps 0-3 = half 0, warps 4-7 = half 1 (tid>>7). Each warp touches only its
// o-half of Wq/Wk/Wv and its ic-half of Wy -> broadcast weight LDS halved.
__global__ void __launch_bounds__(NT, 3) cross_attn_kernel(
    const float* __restrict__ cin, const float* __restrict__ pin,
    const float* __restrict__ Wq,  const float* __restrict__ bq,
    const float* __restrict__ Wk,  const float* __restrict__ bk,
    const float* __restrict__ Wv,  const float* __restrict__ bv,
    const float* __restrict__ Wy,  const float* __restrict__ by,
    float* __restrict__ out)
{
    __shared__ float4   sp4[CH_IN * IMG_W / 4];     // 32KB p row; reused as ybuf
    __shared__ __align__(16) float2 wqT[CH_IN * 8]; // [c][o2] natural o-pairs
    __shared__ __align__(16) float2 wkT[CH_IN * 8];
    __shared__ __align__(16) float2 wvT[CH_IN * 8];
    __shared__ __align__(16) float4 wy_s[CH_IN * CH_Y / 4];
    __shared__ float2   bq2[8], bk2[8], bv2[8];
    __shared__ float    by_s[CH_IN];
    __shared__ uint64_t red[8][4];                  // [warp][local o2]

    const int tid  = threadIdx.x;
    const int t    = tid & 127;       // pixel pair index (float2 slot in row)
    const int half = tid >> 7;        // o-half

    // ---- weight setup: transpose to [c][o2] natural-pair layout ----
    {
        int c = tid >> 3, o2 = tid & 7;              // 256 entries, one each
        wqT[tid] = make_float2(Wq[(2*o2)*CH_IN + c], Wq[(2*o2+1)*CH_IN + c]);
        wkT[tid] = make_float2(Wk[(2*o2)*CH_IN + c], Wk[(2*o2+1)*CH_IN + c]);
        wvT[tid] = make_float2(Wv[(2*o2)*CH_IN + c], Wv[(2*o2+1)*CH_IN + c]);
    }
    if (tid < 128) wy_s[tid] = ((const float4*)Wy)[tid];
    if (tid < 8) {
        bq2[tid] = make_float2(bq[2*tid], bq[2*tid+1]);
        bk2[tid] = make_float2(bk[2*tid], bk[2*tid+1]);
        bv2[tid] = make_float2(bv[2*tid], bv[2*tid+1]);
    }
    if (tid < CH_IN) by_s[tid] = by[tid];

    const int h = blockIdx.x & (IMG_H - 1);
    const int b = blockIdx.x >> 8;
    const size_t base = (size_t)b * CH_IN * CHS + (size_t)h * IMG_W;

    const float4* cg = (const float4*)(cin + base);
    const float4* pg = (const float4*)(pin + base);
    float4* oyg = (float4*)(out + (size_t)b * 2 * CH_IN * CHS + (size_t)h * IMG_W);
    float4* ocg = oyg + (size_t)CH_IN * CHS4;        // concat(c) half

    // ---------------- Phase 1: stage p + concat copy of c ----------------
    {
        float4 cb[8], pb[8];
#pragma unroll
        for (int i = 0; i < 8; i++) {
            int idx = tid + i * NT;                  // = ch*64 + w4
            int ch = idx >> 6, w4 = idx & 63;
            cb[i] = cg[(size_t)ch * CHS4 + w4];
            pb[i] = pg[(size_t)ch * CHS4 + w4];
        }
#pragma unroll
        for (int i = 0; i < 8; i++) {
            int idx = tid + i * NT;
            int ch = idx >> 6, w4 = idx & 63;
            ocg[(size_t)ch * CHS4 + w4] = cb[i];
            sp4[idx] = pb[i];
        }
    }
    __syncthreads();

    // ---------------- q,k projection (my o-half only) ----------------
    const float2* cp2 = (const float2*)(cin + base); // + ch*CHS2 + t
    const float2* sp2 = (const float2*)sp4;          // + ch*128 + t

    uint64_t q[2][4], k[2][4];        // [px][local o2]
#pragma unroll
    for (int ol = 0; ol < 4; ol++) {
        F2U tq; tq.f = bq2[half * 4 + ol];
        F2U tk; tk.f = bk2[half * 4 + ol];
        q[0][ol] = tq.u; q[1][ol] = tq.u;
        k[0][ol] = tk.u; k[1][ol] = tk.u;
    }

#pragma unroll
    for (int c4 = 0; c4 < CH_IN / 4; c4++) {
        float2 cv[4], pv[4];
#pragma unroll
        for (int j = 0; j < 4; j++) {
            int ch = c4 * 4 + j;
            cv[j] = cp2[(size_t)ch * CHS2 + t];      // L2-resident re-read
            pv[j] = sp2[ch * 128 + t];
        }
#pragma unroll
        for (int j = 0; j < 4; j++) {
            const int ch = c4 * 4 + j;
            uint64_t cd0 = dup2(cv[j].x), cd1 = dup2(cv[j].y);
            uint64_t pd0 = dup2(pv[j].x), pd1 = dup2(pv[j].y);
#pragma unroll
            for (int m = 0; m < 2; m++) {            // 2 local o2 per LDS.128
                ulonglong2 wq2 = *(const ulonglong2*)&wqT[ch * 8 + half * 4 + m * 2];
                ulonglong2 wk2 = *(const ulonglong2*)&wkT[ch * 8 + half * 4 + m * 2];
                fma2(q[0][2*m+0], wq2.x, cd0); fma2(q[0][2*m+1], wq2.y, cd0);
                fma2(q[1][2*m+0], wq2.x, cd1); fma2(q[1][2*m+1], wq2.y, cd1);
                fma2(k[0][2*m+0], wk2.x, pd0); fma2(k[0][2*m+1], wk2.y, pd0);
                fma2(k[1][2*m+0], wk2.x, pd1); fma2(k[1][2*m+1], wk2.y, pd1);
            }
        }
    }

    // exp(q*k). No max-subtraction: |q*k| O(1..10); fp32 exp safe, identical
    // after normalization.
    uint64_t e[2][4];
#pragma unroll
    for (int px = 0; px < 2; px++)
#pragma unroll
        for (int ol = 0; ol < 4; ol++) {
            F2U pr; pr.u = mul2(q[px][ol], k[px][ol]);
            e[px][ol] = pack2(__expf(pr.f.x), __expf(pr.f.y));
        }

    // -------- softmax over width: reduce within my o-half (4 warps) --------
    const int lane = tid & 31;
    const int wrp  = tid >> 5;        // warps [4*half, 4*half+4) are my group
#pragma unroll
    for (int ol = 0; ol < 4; ol++) {
        uint64_t s = add2(e[0][ol], e[1][ol]);
#pragma unroll
        for (int d = 16; d > 0; d >>= 1)
            s = add2(s, __shfl_xor_sync(0xffffffffu, (unsigned long long)s, d));
        if (lane == 0) red[wrp][ol] = s;
    }
    __syncthreads();

#pragma unroll
    for (int ol = 0; ol < 4; ol++) {
        F2U tot; tot.u = add2(add2(red[half*4+0][ol], red[half*4+1][ol]),
                              add2(red[half*4+2][ol], red[half*4+3][ol]));
        uint64_t inv = pack2(__frcp_rn(tot.f.x), __frcp_rn(tot.f.y));
        e[0][ol] = mul2(e[0][ol], inv);              // fold 1/sum into e
        e[1][ol] = mul2(e[1][ol], inv);
    }

    // ---------------- v projection (my o-half), y folded in ----------------
    {
        uint64_t v[2][4];
#pragma unroll
        for (int ol = 0; ol < 4; ol++) {
            F2U tv; tv.f = bv2[half * 4 + ol];
            v[0][ol] = tv.u; v[1][ol] = tv.u;
        }
#pragma unroll
        for (int c4 = 0; c4 < CH_IN / 4; c4++) {
            float2 pv[4];
#pragma unroll
            for (int j = 0; j < 4; j++)
                pv[j] = sp2[(c4 * 4 + j) * 128 + t];
#pragma unroll
            for (int j = 0; j < 4; j++) {
                const int ch = c4 * 4 + j;
                uint64_t pd0 = dup2(pv[j].x), pd1 = dup2(pv[j].y);
#pragma unroll
                for (int m = 0; m < 2; m++) {
                    ulonglong2 wv2 = *(const ulonglong2*)&wvT[ch * 8 + half * 4 + m * 2];
                    fma2(v[0][2*m+0], wv2.x, pd0); fma2(v[0][2*m+1], wv2.y, pd0);
                    fma2(v[1][2*m+0], wv2.x, pd1); fma2(v[1][2*m+1], wv2.y, pd1);
                }
            }
        }
#pragma unroll
        for (int px = 0; px < 2; px++)
#pragma unroll
            for (int ol = 0; ol < 4; ol++)
                e[px][ol] = mul2(e[px][ol], v[px][ol]);   // y = softmax * v
    }

    // ---------------- y exchange via smem (overlay dead p region) ----------
    __syncthreads();                  // all p reads done before overwrite
    uint64_t* ybuf = (uint64_t*)sp4;  // [(o2*2+px)][t] : 16KB, conflict-free
#pragma unroll
    for (int ol = 0; ol < 4; ol++) {
        ybuf[((half * 4 + ol) * 2 + 0) * 128 + t] = e[0][ol];
        ybuf[((half * 4 + ol) * 2 + 1) * 128 + t] = e[1][ol];
    }
    __syncthreads();

    uint64_t ya[16];                  // [o2*2+px] : all 16 o for my 2 px
#pragma unroll
    for (int i = 0; i < 16; i++)
        ya[i] = ybuf[i * 128 + t];

    // ---------------- output conv1x1: my ic-half, my 2 px ----------------
    float2* oy2 = (float2*)(out + (size_t)b * 2 * CH_IN * CHS + (size_t)h * IMG_W);
    const ulonglong2* wyu2 = (const ulonglong2*)wy_s;    // 4 per ic, o-pairs
    const int icb = half * 16;
#pragma unroll
    for (int icl = 0; icl < 16; icl++) {
        const int ic = icb + icl;
        uint64_t acc0 = pack2(by_s[ic], 0.f);
        uint64_t acc1 = acc0;
#pragma unroll
        for (int m = 0; m < 4; m++) {
            ulonglong2 w = wyu2[ic * 4 + m];             // o-pairs (2m, 2m+1)
            fma2(acc0, w.x, ya[(2*m+0) * 2 + 0]); fma2(acc0, w.y, ya[(2*m+1) * 2 + 0]);
            fma2(acc1, w.x, ya[(2*m+0) * 2 + 1]); fma2(acc1, w.y, ya[(2*m+1) * 2 + 1]);
        }
        F2U r0, r1; r0.u = acc0; r1.u = acc1;
        oy2[(size_t)ic * CHS2 + t] = make_float2(r0.f.x + r0.f.y, r1.f.x + r1.f.y);
    }
}

extern "C" void kernel_launch(void* const* d_in, const int* in_sizes, int n_in,
                              void* d_out, int out_size)
{
    cross_attn_kernel<<<NB * IMG_H, NT>>>(
        (const float*)d_in[0],  // c
        (const float*)d_in[1],  // p
        (const float*)d_in[2],  // Wq
        (const float*)d_in[3],  // bq
        (const float*)d_in[4],  // Wk
        (const float*)d_in[5],  // bk
        (const float*)d_in[6],  // Wv
        (const float*)d_in[7],  // bv
        (const float*)d_in[8],  // Wy
        (const float*)d_in[9],  // by
        (float*)d_out);
}

// round 12
// speedup vs baseline: 1.8833x; 1.0023x over previous
#include <cuda_runtime.h>
#include <cstdint>

#define CH_IN 32
#define CH_Y  16
#define IMG_H 256
#define IMG_W 256
#define NB    16
#define CHS   (IMG_H * IMG_W)   // channel stride (elements)
#define CHS4  (CHS / 4)
#define CHS2  (CHS / 2)
#define NT    256               // one (b,h) row; thread = (px-pair, o-half)

union F2U { float2 f; uint64_t u; };

// sm_103a packed dual-fp32 ops
__device__ __forceinline__ void fma2(uint64_t& d, uint64_t a, uint64_t b) {
    asm("fma.rn.f32x2 %0, %1, %2, %0;" : "+l"(d) : "l"(a), "l"(b));
}
__device__ __forceinline__ uint64_t mul2(uint64_t a, uint64_t b) {
    uint64_t d; asm("mul.rn.f32x2 %0, %1, %2;" : "=l"(d) : "l"(a), "l"(b)); return d;
}
__device__ __forceinline__ uint64_t add2(uint64_t a, uint64_t b) {
    uint64_t d; asm("add.rn.f32x2 %0, %1, %2;" : "=l"(d) : "l"(a), "l"(b)); return d;
}
__device__ __forceinline__ uint64_t dup2(float x) {
    uint64_t d; asm("mov.b64 %0, {%1, %1};" : "=l"(d) : "f"(x)); return d;
}
__device__ __forceinline__ uint64_t pack2(float lo, float hi) {
    uint64_t d; asm("mov.b64 %0, {%1, %2};" : "=l"(d) : "f"(lo), "f"(hi)); return d;
}

// Thread (t, half): pixels w = 2t, 2t+1; output channels o in [8*half, 8*half+8).
// Warps 0-3 = half 0, warps 4-7 = half 1 (tid>>7). Each warp touches only its
// o-half of Wq/Wk/Wv and its ic-half of Wy -> broadcast weight LDS halved.
__global__ void __launch_bounds__(NT, 3) cross_attn_kernel(
    const float* __restrict__ cin, const float* __restrict__ pin,
    const float* __restrict__ Wq,  const float* __restrict__ bq,
    const float* __restrict__ Wk,  const float* __restrict__ bk,
    const float* __restrict__ Wv,  const float* __restrict__ bv,
    const float* __restrict__ Wy,  const float* __restrict__ by,
    float* __restrict__ out)
{
    __shared__ float4   sp4[CH_IN * IMG_W / 4];     // 32KB p row; reused as ybuf
    __shared__ __align__(16) float2 wqT[CH_IN * 8]; // [c][o2] natural o-pairs
    __shared__ __align__(16) float2 wkT[CH_IN * 8];
    __shared__ __align__(16) float2 wvT[CH_IN * 8];
    __shared__ __align__(16) float4 wy_s[CH_IN * CH_Y / 4];
    __shared__ float2   bq2[8], bk2[8], bv2[8];
    __shared__ float    by_s[CH_IN];
    __shared__ uint64_t red[8][4];                  // [warp][local o2]

    const int tid  = threadIdx.x;
    const int t    = tid & 127;       // pixel pair index (float2 slot in row)
    const int half = tid >> 7;        // o-half

    // ---- weight setup: transpose to [c][o2] natural-pair layout ----
    {
        int c = tid >> 3, o2 = tid & 7;              // 256 entries, one each
        wqT[tid] = make_float2(Wq[(2*o2)*CH_IN + c], Wq[(2*o2+1)*CH_IN + c]);
        wkT[tid] = make_float2(Wk[(2*o2)*CH_IN + c], Wk[(2*o2+1)*CH_IN + c]);
        wvT[tid] = make_float2(Wv[(2*o2)*CH_IN + c], Wv[(2*o2+1)*CH_IN + c]);
    }
    if (tid < 128) wy_s[tid] = ((const float4*)Wy)[tid];
    if (tid < 8) {
        bq2[tid] = make_float2(bq[2*tid], bq[2*tid+1]);
        bk2[tid] = make_float2(bk[2*tid], bk[2*tid+1]);
        bv2[tid] = make_float2(bv[2*tid], bv[2*tid+1]);
    }
    if (tid < CH_IN) by_s[tid] = by[tid];

    const int h = blockIdx.x & (IMG_H - 1);
    const int b = blockIdx.x >> 8;
    const size_t base = (size_t)b * CH_IN * CHS + (size_t)h * IMG_W;

    const float4* cg = (const float4*)(cin + base);
    const float4* pg = (const float4*)(pin + base);
    float4* oyg = (float4*)(out + (size_t)b * 2 * CH_IN * CHS + (size_t)h * IMG_W);
    float4* ocg = oyg + (size_t)CH_IN * CHS4;        // concat(c) half

    // ---------------- Phase 1: stage p + concat copy of c ----------------
    {
        float4 cb[8], pb[8];
#pragma unroll
        for (int i = 0; i < 8; i++) {
            int idx = tid + i * NT;                  // = ch*64 + w4
            int ch = idx >> 6, w4 = idx & 63;
            cb[i] = cg[(size_t)ch * CHS4 + w4];
            pb[i] = pg[(size_t)ch * CHS4 + w4];
        }
#pragma unroll
        for (int i = 0; i < 8; i++) {
            int idx = tid + i * NT;
            int ch = idx >> 6, w4 = idx & 63;
            ocg[(size_t)ch * CHS4 + w4] = cb[i];
            sp4[idx] = pb[i];
        }
    }
    __syncthreads();

    // ---------------- q,k projection (my o-half only) ----------------
    const float2* cp2 = (const float2*)(cin + base); // + ch*CHS2 + t
    const float2* sp2 = (const float2*)sp4;          // + ch*128 + t

    uint64_t q[2][4], k[2][4];        // [px][local o2]
#pragma unroll
    for (int ol = 0; ol < 4; ol++) {
        F2U tq; tq.f = bq2[half * 4 + ol];
        F2U tk; tk.f = bk2[half * 4 + ol];
        q[0][ol] = tq.u; q[1][ol] = tq.u;
        k[0][ol] = tk.u; k[1][ol] = tk.u;
    }

#pragma unroll
    for (int c4 = 0; c4 < CH_IN / 4; c4++) {
        float2 cv[4], pv[4];
#pragma unroll
        for (int j = 0; j < 4; j++) {
            int ch = c4 * 4 + j;
            cv[j] = cp2[(size_t)ch * CHS2 + t];      // L2-resident re-read
            pv[j] = sp2[ch * 128 + t];
        }
#pragma unroll
        for (int j = 0; j < 4; j++) {
            const int ch = c4 * 4 + j;
            uint64_t cd0 = dup2(cv[j].x), cd1 = dup2(cv[j].y);
            uint64_t pd0 = dup2(pv[j].x), pd1 = dup2(pv[j].y);
#pragma unroll
            for (int m = 0; m < 2; m++) {            // 2 local o2 per LDS.128
                ulonglong2 wq2 = *(const ulonglong2*)&wqT[ch * 8 + half * 4 + m * 2];
                ulonglong2 wk2 = *(const ulonglong2*)&wkT[ch * 8 + half * 4 + m * 2];
                fma2(q[0][2*m+0], wq2.x, cd0); fma2(q[0][2*m+1], wq2.y, cd0);
                fma2(q[1][2*m+0], wq2.x, cd1); fma2(q[1][2*m+1], wq2.y, cd1);
                fma2(k[0][2*m+0], wk2.x, pd0); fma2(k[0][2*m+1], wk2.y, pd0);
                fma2(k[1][2*m+0], wk2.x, pd1); fma2(k[1][2*m+1], wk2.y, pd1);
            }
        }
    }

    // exp(q*k). No max-subtraction: |q*k| O(1..10); fp32 exp safe, identical
    // after normalization.
    uint64_t e[2][4];
#pragma unroll
    for (int px = 0; px < 2; px++)
#pragma unroll
        for (int ol = 0; ol < 4; ol++) {
            F2U pr; pr.u = mul2(q[px][ol], k[px][ol]);
            e[px][ol] = pack2(__expf(pr.f.x), __expf(pr.f.y));
        }

    // -------- softmax over width: reduce within my o-half (4 warps) --------
    const int lane = tid & 31;
    const int wrp  = tid >> 5;        // warps [4*half, 4*half+4) are my group
#pragma unroll
    for (int ol = 0; ol < 4; ol++) {
        uint64_t s = add2(e[0][ol], e[1][ol]);
#pragma unroll
        for (int d = 16; d > 0; d >>= 1)
            s = add2(s, __shfl_xor_sync(0xffffffffu, (unsigned long long)s, d));
        if (lane == 0) red[wrp][ol] = s;
    }
    __syncthreads();

#pragma unroll
    for (int ol = 0; ol < 4; ol++) {
        F2U tot; tot.u = add2(add2(red[half*4+0][ol], red[half*4+1][ol]),
                              add2(red[half*4+2][ol], red[half*4+3][ol]));
        uint64_t inv = pack2(__frcp_rn(tot.f.x), __frcp_rn(tot.f.y));
        e[0][ol] = mul2(e[0][ol], inv);              // fold 1/sum into e
        e[1][ol] = mul2(e[1][ol], inv);
    }

    // ---------------- v projection (my o-half), y folded in ----------------
    {
        uint64_t v[2][4];
#pragma unroll
        for (int ol = 0; ol < 4; ol++) {
            F2U tv; tv.f = bv2[half * 4 + ol];
            v[0][ol] = tv.u; v[1][ol] = tv.u;
        }
#pragma unroll
        for (int c4 = 0; c4 < CH_IN / 4; c4++) {
            float2 pv[4];
#pragma unroll
            for (int j = 0; j < 4; j++)
                pv[j] = sp2[(c4 * 4 + j) * 128 + t];
#pragma unroll
            for (int j = 0; j < 4; j++) {
                const int ch = c4 * 4 + j;
                uint64_t pd0 = dup2(pv[j].x), pd1 = dup2(pv[j].y);
#pragma unroll
                for (int m = 0; m < 2; m++) {
                    ulonglong2 wv2 = *(const ulonglong2*)&wvT[ch * 8 + half * 4 + m * 2];
                    fma2(v[0][2*m+0], wv2.x, pd0); fma2(v[0][2*m+1], wv2.y, pd0);
                    fma2(v[1][2*m+0], wv2.x, pd1); fma2(v[1][2*m+1], wv2.y, pd1);
                }
            }
        }
#pragma unroll
        for (int px = 0; px < 2; px++)
#pragma unroll
            for (int ol = 0; ol < 4; ol++)
                e[px][ol] = mul2(e[px][ol], v[px][ol]);   // y = softmax * v
    }

    // ---------------- y exchange via smem (overlay dead p region) ----------
    __syncthreads();                  // all p reads done before overwrite
    uint64_t* ybuf = (uint64_t*)sp4;  // [(o2*2+px)][t] : 16KB, conflict-free
#pragma unroll
    for (int ol = 0; ol < 4; ol++) {
        ybuf[((half * 4 + ol) * 2 + 0) * 128 + t] = e[0][ol];
        ybuf[((half * 4 + ol) * 2 + 1) * 128 + t] = e[1][ol];
    }
    __syncthreads();

    uint64_t ya[16];                  // [o2*2+px] : all 16 o for my 2 px
#pragma unroll
    for (int i = 0; i < 16; i++)
        ya[i] = ybuf[i * 128 + t];

    // ---------------- output conv1x1: my ic-half, my 2 px ----------------
    float2* oy2 = (float2*)(out + (size_t)b * 2 * CH_IN * CHS + (size_t)h * IMG_W);
    const ulonglong2* wyu2 = (const ulonglong2*)wy_s;    // 4 per ic, o-pairs
    const int icb = half * 16;
#pragma unroll
    for (int icl = 0; icl < 16; icl++) {
        const int ic = icb + icl;
        uint64_t acc0 = pack2(by_s[ic], 0.f);
        uint64_t acc1 = acc0;
#pragma unroll
        for (int m = 0; m < 4; m++) {
            ulonglong2 w = wyu2[ic * 4 + m];             // o-pairs (2m, 2m+1)
            fma2(acc0, w.x, ya[(2*m+0) * 2 + 0]); fma2(acc0, w.y, ya[(2*m+1) * 2 + 0]);
            fma2(acc1, w.x, ya[(2*m+0) * 2 + 1]); fma2(acc1, w.y, ya[(2*m+1) * 2 + 1]);
        }
        F2U r0, r1; r0.u = acc0; r1.u = acc1;
        oy2[(size_t)ic * CHS2 + t] = make_float2(r0.f.x + r0.f.y, r1.f.x + r1.f.y);
    }
}

extern "C" void kernel_launch(void* const* d_in, const int* in_sizes, int n_in,
                              void* d_out, int out_size)
{
    cross_attn_kernel<<<NB * IMG_H, NT>>>(
        (const float*)d_in[0],  // c
        (const float*)d_in[1],  // p
        (const float*)d_in[2],  // Wq
        (const float*)d_in[3],  // bq
        (const float*)d_in[4],  // Wk
        (const float*)d_in[5],  // bk
        (const float*)d_in[6],  // Wv
        (const float*)d_in[7],  // bv
        (const float*)d_in[8],  // Wy
        (const float*)d_in[9],  // by
        (float*)d_out);
}